// round 5
// baseline (speedup 1.0000x reference)
#include <cuda_runtime.h>

#define D_MODEL 1024
#define NHEAD   16
#define DK      64
#define SEQ     2048
#define BATCH   4
#define MROWS   (BATCH * SEQ)   // 8192

// Scratch (allocation-free rule: __device__ globals)
__device__ float g_Q[BATCH * NHEAD * SEQ * DK];   // [B,H,n,dk]
__device__ float g_K[BATCH * NHEAD * SEQ * DK];
__device__ float g_V[BATCH * NHEAD * SEQ * DK];
__device__ float g_AO[BATCH * SEQ * D_MODEL];     // attention out, [B,n,D]

// ---------------------------------------------------------------------------
// TN SGEMM: C[m,n] = sum_k A[m,k] * W[n,k] + bias[n]
// A: [M=8192, K=1024] row-major, W: [N=1024, K=1024] row-major.
// Tile 128x128x16, 256 threads, 8x8 per thread (split 4+4 pattern).
// HEADOUT: write C into [B, H, n, dk] layout instead of [M, N].
// ---------------------------------------------------------------------------
template <bool HEADOUT>
__global__ __launch_bounds__(256) void gemm_tn(
    const float* __restrict__ A, const float* __restrict__ W,
    const float* __restrict__ bias, float* __restrict__ C)
{
    const int K = D_MODEL;
    __shared__ float As[16][132];   // As[k][m]
    __shared__ float Bs[16][132];   // Bs[k][n]

    const int tid = threadIdx.x;
    const int tx = tid & 15;
    const int ty = tid >> 4;
    const int row0 = blockIdx.y * 128;
    const int col0 = blockIdx.x * 128;

    const float* Ag = A + (size_t)row0 * K;
    const float* Wg = W + (size_t)col0 * K;

    float acc[8][8];
#pragma unroll
    for (int i = 0; i < 8; i++)
#pragma unroll
        for (int j = 0; j < 8; j++) acc[i][j] = 0.0f;

    for (int k0 = 0; k0 < K; k0 += 16) {
#pragma unroll
        for (int t = 0; t < 2; t++) {
            int idx = tid + t * 256;          // 0..511
            int r   = idx >> 2;               // 0..127
            int c4  = (idx & 3) * 4;          // 0,4,8,12
            float4 a = *(const float4*)(Ag + (size_t)r * K + k0 + c4);
            As[c4 + 0][r] = a.x; As[c4 + 1][r] = a.y;
            As[c4 + 2][r] = a.z; As[c4 + 3][r] = a.w;
            float4 b = *(const float4*)(Wg + (size_t)r * K + k0 + c4);
            Bs[c4 + 0][r] = b.x; Bs[c4 + 1][r] = b.y;
            Bs[c4 + 2][r] = b.z; Bs[c4 + 3][r] = b.w;
        }
        __syncthreads();

#pragma unroll
        for (int kk = 0; kk < 16; kk++) {
            float a[8], b[8];
#pragma unroll
            for (int i = 0; i < 4; i++) {
                a[i]     = As[kk][ty * 4 + i];
                a[i + 4] = As[kk][64 + ty * 4 + i];
                b[i]     = Bs[kk][tx * 4 + i];
                b[i + 4] = Bs[kk][64 + tx * 4 + i];
            }
#pragma unroll
            for (int i = 0; i < 8; i++)
#pragma unroll
                for (int j = 0; j < 8; j++)
                    acc[i][j] = fmaf(a[i], b[j], acc[i][j]);
        }
        __syncthreads();
    }

    // Epilogue
#pragma unroll
    for (int i = 0; i < 8; i++) {
        int r = row0 + ((i < 4) ? (ty * 4 + i) : (64 + ty * 4 + (i - 4)));
#pragma unroll
        for (int j = 0; j < 8; j++) {
            int c = col0 + ((j < 4) ? (tx * 4 + j) : (64 + tx * 4 + (j - 4)));
            float v = acc[i][j] + bias[c];
            if (HEADOUT) {
                int b  = r >> 11;        // / SEQ
                int ii = r & (SEQ - 1);
                int h  = c >> 6;         // / DK
                int d  = c & (DK - 1);
                g_dummy_store:
                C[(((size_t)(b * NHEAD + h)) * SEQ + ii) * DK + d] = v;
            } else {
                C[(size_t)r * D_MODEL + c] = v;
            }
        }
    }
}

// ---------------------------------------------------------------------------
// Flash attention, fp32. One CTA = one (b,h) x 128 q-rows. BN=64 kv per iter.
// 256 threads: (ty, tx) = 16x16; S tile rows split 4+4 per thread, cols tx*4+j.
// ---------------------------------------------------------------------------
__global__ __launch_bounds__(256) void flash_attn(
    const float* __restrict__ Q, const float* __restrict__ Kg,
    const float* __restrict__ V, float* __restrict__ O)
{
    extern __shared__ float sm[];
    float* Qs = sm;                     // [64][129]  Qs[d][r]
    float* Ks = Qs + 64 * 129;          // [64][65]   Ks[d][c]
    float* Vs = Ks + 64 * 65;           // [64][64]   Vs[k][c]
    float* Ps = Vs + 64 * 64;           // [128][65]  Ps[r][k]

    const int tid = threadIdx.x;
    const int tx = tid & 15;
    const int ty = tid >> 4;
    const int bh = blockIdx.y;          // 0..63
    const int q0 = blockIdx.x * 128;

    const float* Qp = Q  + ((size_t)bh * SEQ + q0) * DK;
    const float* Kp = Kg + (size_t)bh * SEQ * DK;
    const float* Vp = V  + (size_t)bh * SEQ * DK;

    // Load Q tile [128][64] transposed into Qs[d][r]
#pragma unroll
    for (int t = 0; t < 8; t++) {
        int idx = tid + t * 256;          // 0..2047 float4 indices
        int r   = idx >> 4;               // 16 float4 per row
        int c4  = (idx & 15) * 4;
        float4 q = *(const float4*)(Qp + (size_t)r * DK + c4);
        Qs[(c4 + 0) * 129 + r] = q.x;
        Qs[(c4 + 1) * 129 + r] = q.y;
        Qs[(c4 + 2) * 129 + r] = q.z;
        Qs[(c4 + 3) * 129 + r] = q.w;
    }

    float m_i[8], l_i[8], acc[8][4];
#pragma unroll
    for (int i = 0; i < 8; i++) {
        m_i[i] = -1e30f;
        l_i[i] = 0.0f;
#pragma unroll
        for (int j = 0; j < 4; j++) acc[i][j] = 0.0f;
    }

    const float scale = 0.125f;   // 1/sqrt(64)

    for (int kt = 0; kt < SEQ; kt += 64) {
        __syncthreads();   // Q ready (iter 0); prev iter's Ps/Vs reads done

        // Load K tile transposed Ks[d][c], V tile Vs[k][c]
#pragma unroll
        for (int t = 0; t < 4; t++) {
            int idx = tid + t * 256;        // 0..1023
            int r   = idx >> 4;             // kv row within tile 0..63
            int c4  = (idx & 15) * 4;
            float4 kk = *(const float4*)(Kp + (size_t)(kt + r) * DK + c4);
            Ks[(c4 + 0) * 65 + r] = kk.x;
            Ks[(c4 + 1) * 65 + r] = kk.y;
            Ks[(c4 + 2) * 65 + r] = kk.z;
            Ks[(c4 + 3) * 65 + r] = kk.w;
            float4 vv = *(const float4*)(Vp + (size_t)(kt + r) * DK + c4);
            *(float4*)(Vs + r * 64 + c4) = vv;
        }
        __syncthreads();

        // S = Q * K^T (scaled)
        float s[8][4];
#pragma unroll
        for (int i = 0; i < 8; i++)
#pragma unroll
            for (int j = 0; j < 4; j++) s[i][j] = 0.0f;

#pragma unroll 8
        for (int d = 0; d < 64; d++) {
            float a[8], b[4];
#pragma unroll
            for (int i = 0; i < 4; i++) {
                a[i]     = Qs[d * 129 + ty * 4 + i];
                a[i + 4] = Qs[d * 129 + 64 + ty * 4 + i];
            }
#pragma unroll
            for (int j = 0; j < 4; j++) b[j] = Ks[d * 65 + tx * 4 + j];
#pragma unroll
            for (int i = 0; i < 8; i++)
#pragma unroll
                for (int j = 0; j < 4; j++)
                    s[i][j] = fmaf(a[i], b[j], s[i][j]);
        }

        // Online softmax (rows owned by 16 tx lanes; shfl within 16-lane groups)
#pragma unroll
        for (int i = 0; i < 8; i++) {
            int rloc = (i < 4) ? (ty * 4 + i) : (64 + ty * 4 + (i - 4));
#pragma unroll
            for (int j = 0; j < 4; j++) s[i][j] *= scale;

            float mx = fmaxf(fmaxf(s[i][0], s[i][1]), fmaxf(s[i][2], s[i][3]));
            mx = fmaxf(mx, __shfl_xor_sync(0xffffffffu, mx, 1, 16));
            mx = fmaxf(mx, __shfl_xor_sync(0xffffffffu, mx, 2, 16));
            mx = fmaxf(mx, __shfl_xor_sync(0xffffffffu, mx, 4, 16));
            mx = fmaxf(mx, __shfl_xor_sync(0xffffffffu, mx, 8, 16));

            float mnew  = fmaxf(m_i[i], mx);
            float alpha = __expf(m_i[i] - mnew);
            m_i[i] = mnew;

            float rs = 0.0f;
#pragma unroll
            for (int j = 0; j < 4; j++) {
                float p = __expf(s[i][j] - mnew);
                Ps[rloc * 65 + tx * 4 + j] = p;
                rs += p;
            }
            rs += __shfl_xor_sync(0xffffffffu, rs, 1, 16);
            rs += __shfl_xor_sync(0xffffffffu, rs, 2, 16);
            rs += __shfl_xor_sync(0xffffffffu, rs, 4, 16);
            rs += __shfl_xor_sync(0xffffffffu, rs, 8, 16);

            l_i[i] = l_i[i] * alpha + rs;
#pragma unroll
            for (int j = 0; j < 4; j++) acc[i][j] *= alpha;
        }
        __syncthreads();

        // O += P * V
#pragma unroll 8
        for (int k = 0; k < 64; k++) {
            float v[4];
#pragma unroll
            for (int j = 0; j < 4; j++) v[j] = Vs[k * 64 + tx * 4 + j];
#pragma unroll
            for (int i = 0; i < 8; i++) {
                int rloc = (i < 4) ? (ty * 4 + i) : (64 + ty * 4 + (i - 4));
                float p = Ps[rloc * 65 + k];
#pragma unroll
                for (int j = 0; j < 4; j++)
                    acc[i][j] = fmaf(p, v[j], acc[i][j]);
            }
        }
    }

    // Write out in [B, n, D_MODEL] layout
    const int b = bh >> 4;
    const int h = bh & (NHEAD - 1);
#pragma unroll
    for (int i = 0; i < 8; i++) {
        int rloc = (i < 4) ? (ty * 4 + i) : (64 + ty * 4 + (i - 4));
        int r = q0 + rloc;
        float inv = 1.0f / l_i[i];
        float* Op = O + ((size_t)b * SEQ + r) * D_MODEL + h * DK + tx * 4;
#pragma unroll
        for (int j = 0; j < 4; j++) Op[j] = acc[i][j] * inv;
    }
}

// ---------------------------------------------------------------------------
extern "C" void kernel_launch(void* const* d_in, const int* in_sizes, int n_in,
                              void* d_out, int out_size)
{
    const float* X  = (const float*)d_in[0];
    const float* Wq = (const float*)d_in[1];
    const float* bq = (const float*)d_in[2];
    const float* Wk = (const float*)d_in[3];
    const float* bk = (const float*)d_in[4];
    const float* Wv = (const float*)d_in[5];
    const float* bv = (const float*)d_in[6];
    const float* Wo = (const float*)d_in[7];
    const float* bo = (const float*)d_in[8];
    float* out = (float*)d_out;

    float *Qp, *Kp, *Vp, *AOp;
    cudaGetSymbolAddress((void**)&Qp,  g_Q);
    cudaGetSymbolAddress((void**)&Kp,  g_K);
    cudaGetSymbolAddress((void**)&Vp,  g_V);
    cudaGetSymbolAddress((void**)&AOp, g_AO);

    dim3 gg(D_MODEL / 128, MROWS / 128);   // (8, 64)
    dim3 blk(256);

    gemm_tn<true><<<gg, blk>>>(X, Wq, bq, Qp);
    gemm_tn<true><<<gg, blk>>>(X, Wk, bk, Kp);
    gemm_tn<true><<<gg, blk>>>(X, Wv, bv, Vp);

    const int smem = (64 * 129 + 64 * 65 + 64 * 64 + 128 * 65) * 4;  // 99328
    cudaFuncSetAttribute(flash_attn, cudaFuncAttributeMaxDynamicSharedMemorySize, smem);
    flash_attn<<<dim3(SEQ / 128, BATCH * NHEAD), blk, smem>>>(Qp, Kp, Vp, AOp);

    gemm_tn<false><<<gg, blk>>>(AOp, Wo, bo, out);
}

// round 7
// speedup vs baseline: 1.4385x; 1.4385x over previous
#include <cuda_runtime.h>
#include <cstdint>

#define D_MODEL 1024
#define NHEAD   16
#define DK      64
#define SEQ     2048
#define BATCH   4
#define MROWS   (BATCH * SEQ)   // 8192

// ---------------------------------------------------------------------------
// Scratch (allocation-free rule: __device__ globals)
// ---------------------------------------------------------------------------
__device__ float g_Q[BATCH * NHEAD * SEQ * DK];   // [B,H,n,dk]
__device__ float g_K[BATCH * NHEAD * SEQ * DK];
__device__ float g_V[BATCH * NHEAD * SEQ * DK];
__device__ float g_AO[BATCH * SEQ * D_MODEL];     // attention out, [B,n,D]
__device__ float g_Xc[MROWS * D_MODEL];           // tf32-rounded X
__device__ float g_Wqc[D_MODEL * D_MODEL];
__device__ float g_Wkc[D_MODEL * D_MODEL];
__device__ float g_Wvc[D_MODEL * D_MODEL];
__device__ float g_Woc[D_MODEL * D_MODEL];

// ---------------------------------------------------------------------------
// helpers
// ---------------------------------------------------------------------------
__device__ __forceinline__ uint32_t smem_u32(const void* p) {
    uint32_t a;
    asm("{ .reg .u64 t; cvta.to.shared.u64 t, %1; cvt.u32.u64 %0, t; }"
        : "=r"(a) : "l"(p));
    return a;
}

__device__ __forceinline__ void cp_async16(uint32_t dst, const void* src) {
    asm volatile("cp.async.cg.shared.global [%0], [%1], 16;\n" :: "r"(dst), "l"(src));
}
#define CP_COMMIT()  asm volatile("cp.async.commit_group;\n" ::: "memory")
#define CP_WAIT(N)   asm volatile("cp.async.wait_group %0;\n" :: "n"(N) : "memory")

__device__ __forceinline__ void mma_tf32(float* c, const float* a, const float* b) {
    asm volatile(
        "mma.sync.aligned.m16n8k8.row.col.f32.tf32.tf32.f32 "
        "{%0,%1,%2,%3}, {%4,%5,%6,%7}, {%8,%9}, {%0,%1,%2,%3};"
        : "+f"(c[0]), "+f"(c[1]), "+f"(c[2]), "+f"(c[3])
        : "r"(__float_as_uint(a[0])), "r"(__float_as_uint(a[1])),
          "r"(__float_as_uint(a[2])), "r"(__float_as_uint(a[3])),
          "r"(__float_as_uint(b[0])), "r"(__float_as_uint(b[1])));
}

// ---------------------------------------------------------------------------
// Elementwise tf32 RNA rounding (unbiased): HMMA truncates operands to tf32;
// truncation of an already-RNA-rounded value is exact, so the GEMM error is
// zero-mean instead of a systematic ~7e-4 shrink.
// ---------------------------------------------------------------------------
__global__ void round_tf32(const float* __restrict__ in, float* __restrict__ out, int n4) {
    int i = blockIdx.x * blockDim.x + threadIdx.x;
    if (i < n4) {
        float4 v = ((const float4*)in)[i];
        uint32_t a, b, c, d;
        asm("cvt.rna.tf32.f32 %0, %1;" : "=r"(a) : "f"(v.x));
        asm("cvt.rna.tf32.f32 %0, %1;" : "=r"(b) : "f"(v.y));
        asm("cvt.rna.tf32.f32 %0, %1;" : "=r"(c) : "f"(v.z));
        asm("cvt.rna.tf32.f32 %0, %1;" : "=r"(d) : "f"(v.w));
        float4 o;
        o.x = __uint_as_float(a); o.y = __uint_as_float(b);
        o.z = __uint_as_float(c); o.w = __uint_as_float(d);
        ((float4*)out)[i] = o;
    }
}

// ---------------------------------------------------------------------------
// TN GEMM on mma.sync tf32: C[m,n] = sum_k A[m,k] * W[n,k] + bias[n]
// CTA tile 128x128, BK=16, 256 threads (8 warps, 2x4 grid, warp tile 64x32).
// Double-buffered cp.async. Smem rows padded to 20 floats -> conflict-free
// fragment loads (8 rows x 4 cols hit 32 distinct banks at stride 20).
// HEADOUT writes C into [B,H,n,dk] layout.
// ---------------------------------------------------------------------------
#define PAD 20

template <bool HEADOUT>
__global__ void __launch_bounds__(256) gemm_tf32mma(
    const float* __restrict__ A, const float* __restrict__ W,
    const float* __restrict__ bias, float* __restrict__ C)
{
    __shared__ float sA[2][128 * PAD];
    __shared__ float sB[2][128 * PAD];

    const int K = D_MODEL;
    const int tid = threadIdx.x;
    const int wid = tid >> 5;
    const int lid = tid & 31;
    const int warpM = wid >> 2;          // 0..1
    const int warpN = wid & 3;           // 0..3
    const int grp = lid >> 2;            // 0..7
    const int tig = lid & 3;             // 0..3
    const int row0 = blockIdx.y * 128;
    const int col0 = blockIdx.x * 128;

    const float* Ag = A + (size_t)row0 * K;
    const float* Wg = W + (size_t)col0 * K;

    const uint32_t aBase = smem_u32(sA);
    const uint32_t bBase = smem_u32(sB);

    // loader mapping: thread covers row tid>>1, 8 floats starting (tid&1)*8
    const int lr = tid >> 1;
    const int lc = (tid & 1) * 8;
    const uint32_t ldst = (uint32_t)(lr * PAD + lc) * 4;

    float acc[4][4][4];
#pragma unroll
    for (int mt = 0; mt < 4; mt++)
#pragma unroll
        for (int nt = 0; nt < 4; nt++)
#pragma unroll
            for (int j = 0; j < 4; j++) acc[mt][nt][j] = 0.0f;

    // prologue: chunk 0 -> stage 0
    {
        cp_async16(aBase + ldst,      Ag + (size_t)lr * K + lc);
        cp_async16(aBase + ldst + 16, Ag + (size_t)lr * K + lc + 4);
        cp_async16(bBase + ldst,      Wg + (size_t)lr * K + lc);
        cp_async16(bBase + ldst + 16, Wg + (size_t)lr * K + lc + 4);
        CP_COMMIT();
    }

    const int NC = K / 16;   // 64
#pragma unroll 1
    for (int c = 0; c < NC; c++) {
        const int s = c & 1;
        if (c + 1 < NC) {
            const uint32_t soff = (uint32_t)((s ^ 1) * 128 * PAD) * 4;
            const int k0 = (c + 1) * 16;
            cp_async16(aBase + soff + ldst,      Ag + (size_t)lr * K + k0 + lc);
            cp_async16(aBase + soff + ldst + 16, Ag + (size_t)lr * K + k0 + lc + 4);
            cp_async16(bBase + soff + ldst,      Wg + (size_t)lr * K + k0 + lc);
            cp_async16(bBase + soff + ldst + 16, Wg + (size_t)lr * K + k0 + lc + 4);
            CP_COMMIT();
            CP_WAIT(1);
        } else {
            CP_WAIT(0);
        }
        __syncthreads();

        const float* Ab = sA[s];
        const float* Bb = sB[s];
#pragma unroll
        for (int ks = 0; ks < 2; ks++) {
            const int kb = ks * 8;
            float af[4][4];
#pragma unroll
            for (int mt = 0; mt < 4; mt++) {
                const int rb = warpM * 64 + mt * 16;
                af[mt][0] = Ab[(rb + grp)     * PAD + kb + tig];
                af[mt][1] = Ab[(rb + grp + 8) * PAD + kb + tig];
                af[mt][2] = Ab[(rb + grp)     * PAD + kb + tig + 4];
                af[mt][3] = Ab[(rb + grp + 8) * PAD + kb + tig + 4];
            }
            float bf[4][2];
#pragma unroll
            for (int nt = 0; nt < 4; nt++) {
                const int cb = warpN * 32 + nt * 8;
                bf[nt][0] = Bb[(cb + grp) * PAD + kb + tig];
                bf[nt][1] = Bb[(cb + grp) * PAD + kb + tig + 4];
            }
#pragma unroll
            for (int mt = 0; mt < 4; mt++)
#pragma unroll
                for (int nt = 0; nt < 4; nt++)
                    mma_tf32(acc[mt][nt], af[mt], bf[nt]);
        }
        __syncthreads();
    }

    // epilogue: c0/c1 are adjacent columns -> float2 stores
#pragma unroll
    for (int mt = 0; mt < 4; mt++) {
#pragma unroll
        for (int nt = 0; nt < 4; nt++) {
            const int r  = row0 + warpM * 64 + mt * 16 + grp;
            const int cc = col0 + warpN * 32 + nt * 8 + tig * 2;
            const float b0 = bias[cc], b1 = bias[cc + 1];

            float2 v01 = make_float2(acc[mt][nt][0] + b0, acc[mt][nt][1] + b1);
            float2 v23 = make_float2(acc[mt][nt][2] + b0, acc[mt][nt][3] + b1);

            if (HEADOUT) {
                const int b  = r >> 11;
                const int h  = cc >> 6;
                const int d0 = cc & (DK - 1);
                const size_t base = ((size_t)(b * NHEAD + h) * SEQ);
                *(float2*)(C + (base + (r & (SEQ - 1)))     * DK + d0) = v01;
                *(float2*)(C + (base + ((r + 8) & (SEQ-1))) * DK + d0) = v23;
            } else {
                *(float2*)(C + (size_t)r * D_MODEL + cc)       = v01;
                *(float2*)(C + (size_t)(r + 8) * D_MODEL + cc) = v23;
            }
        }
    }
}

// ---------------------------------------------------------------------------
// Flash attention, fp32 (unchanged from passing baseline).
// ---------------------------------------------------------------------------
__global__ __launch_bounds__(256) void flash_attn(
    const float* __restrict__ Q, const float* __restrict__ Kg,
    const float* __restrict__ V, float* __restrict__ O)
{
    extern __shared__ float sm[];
    float* Qs = sm;                     // [64][129]  Qs[d][r]
    float* Ks = Qs + 64 * 129;          // [64][65]   Ks[d][c]
    float* Vs = Ks + 64 * 65;           // [64][64]   Vs[k][c]
    float* Ps = Vs + 64 * 64;           // [128][65]  Ps[r][k]

    const int tid = threadIdx.x;
    const int tx = tid & 15;
    const int ty = tid >> 4;
    const int bh = blockIdx.y;          // 0..63
    const int q0 = blockIdx.x * 128;

    const float* Qp = Q  + ((size_t)bh * SEQ + q0) * DK;
    const float* Kp = Kg + (size_t)bh * SEQ * DK;
    const float* Vp = V  + (size_t)bh * SEQ * DK;

#pragma unroll
    for (int t = 0; t < 8; t++) {
        int idx = tid + t * 256;
        int r   = idx >> 4;
        int c4  = (idx & 15) * 4;
        float4 q = *(const float4*)(Qp + (size_t)r * DK + c4);
        Qs[(c4 + 0) * 129 + r] = q.x;
        Qs[(c4 + 1) * 129 + r] = q.y;
        Qs[(c4 + 2) * 129 + r] = q.z;
        Qs[(c4 + 3) * 129 + r] = q.w;
    }

    float m_i[8], l_i[8], acc[8][4];
#pragma unroll
    for (int i = 0; i < 8; i++) {
        m_i[i] = -1e30f;
        l_i[i] = 0.0f;
#pragma unroll
        for (int j = 0; j < 4; j++) acc[i][j] = 0.0f;
    }

    const float scale = 0.125f;

    for (int kt = 0; kt < SEQ; kt += 64) {
        __syncthreads();

#pragma unroll
        for (int t = 0; t < 4; t++) {
            int idx = tid + t * 256;
            int r   = idx >> 4;
            int c4  = (idx & 15) * 4;
            float4 kk = *(const float4*)(Kp + (size_t)(kt + r) * DK + c4);
            Ks[(c4 + 0) * 65 + r] = kk.x;
            Ks[(c4 + 1) * 65 + r] = kk.y;
            Ks[(c4 + 2) * 65 + r] = kk.z;
            Ks[(c4 + 3) * 65 + r] = kk.w;
            float4 vv = *(const float4*)(Vp + (size_t)(kt + r) * DK + c4);
            *(float4*)(Vs + r * 64 + c4) = vv;
        }
        __syncthreads();

        float s[8][4];
#pragma unroll
        for (int i = 0; i < 8; i++)
#pragma unroll
            for (int j = 0; j < 4; j++) s[i][j] = 0.0f;

#pragma unroll 8
        for (int d = 0; d < 64; d++) {
            float a[8], b[4];
#pragma unroll
            for (int i = 0; i < 4; i++) {
                a[i]     = Qs[d * 129 + ty * 4 + i];
                a[i + 4] = Qs[d * 129 + 64 + ty * 4 + i];
            }
#pragma unroll
            for (int j = 0; j < 4; j++) b[j] = Ks[d * 65 + tx * 4 + j];
#pragma unroll
            for (int i = 0; i < 8; i++)
#pragma unroll
                for (int j = 0; j < 4; j++)
                    s[i][j] = fmaf(a[i], b[j], s[i][j]);
        }

#pragma unroll
        for (int i = 0; i < 8; i++) {
            int rloc = (i < 4) ? (ty * 4 + i) : (64 + ty * 4 + (i - 4));
#pragma unroll
            for (int j = 0; j < 4; j++) s[i][j] *= scale;

            float mx = fmaxf(fmaxf(s[i][0], s[i][1]), fmaxf(s[i][2], s[i][3]));
            mx = fmaxf(mx, __shfl_xor_sync(0xffffffffu, mx, 1, 16));
            mx = fmaxf(mx, __shfl_xor_sync(0xffffffffu, mx, 2, 16));
            mx = fmaxf(mx, __shfl_xor_sync(0xffffffffu, mx, 4, 16));
            mx = fmaxf(mx, __shfl_xor_sync(0xffffffffu, mx, 8, 16));

            float mnew  = fmaxf(m_i[i], mx);
            float alpha = __expf(m_i[i] - mnew);
            m_i[i] = mnew;

            float rs = 0.0f;
#pragma unroll
            for (int j = 0; j < 4; j++) {
                float p = __expf(s[i][j] - mnew);
                Ps[rloc * 65 + tx * 4 + j] = p;
                rs += p;
            }
            rs += __shfl_xor_sync(0xffffffffu, rs, 1, 16);
            rs += __shfl_xor_sync(0xffffffffu, rs, 2, 16);
            rs += __shfl_xor_sync(0xffffffffu, rs, 4, 16);
            rs += __shfl_xor_sync(0xffffffffu, rs, 8, 16);

            l_i[i] = l_i[i] * alpha + rs;
#pragma unroll
            for (int j = 0; j < 4; j++) acc[i][j] *= alpha;
        }
        __syncthreads();

#pragma unroll 8
        for (int k = 0; k < 64; k++) {
            float v[4];
#pragma unroll
            for (int j = 0; j < 4; j++) v[j] = Vs[k * 64 + tx * 4 + j];
#pragma unroll
            for (int i = 0; i < 8; i++) {
                int rloc = (i < 4) ? (ty * 4 + i) : (64 + ty * 4 + (i - 4));
                float p = Ps[rloc * 65 + k];
#pragma unroll
                for (int j = 0; j < 4; j++)
                    acc[i][j] = fmaf(p, v[j], acc[i][j]);
            }
        }
    }

    const int b = bh >> 4;
    const int h = bh & (NHEAD - 1);
#pragma unroll
    for (int i = 0; i < 8; i++) {
        int rloc = (i < 4) ? (ty * 4 + i) : (64 + ty * 4 + (i - 4));
        int r = q0 + rloc;
        float inv = 1.0f / l_i[i];
        float* Op = O + ((size_t)b * SEQ + r) * D_MODEL + h * DK + tx * 4;
#pragma unroll
        for (int j = 0; j < 4; j++) Op[j] = acc[i][j] * inv;
    }
}

// ---------------------------------------------------------------------------
extern "C" void kernel_launch(void* const* d_in, const int* in_sizes, int n_in,
                              void* d_out, int out_size)
{
    const float* X  = (const float*)d_in[0];
    const float* Wq = (const float*)d_in[1];
    const float* bq = (const float*)d_in[2];
    const float* Wk = (const float*)d_in[3];
    const float* bk = (const float*)d_in[4];
    const float* Wv = (const float*)d_in[5];
    const float* bv = (const float*)d_in[6];
    const float* Wo = (const float*)d_in[7];
    const float* bo = (const float*)d_in[8];
    float* out = (float*)d_out;

    float *Qp, *Kp, *Vp, *AOp, *Xc, *Wqc, *Wkc, *Wvc, *Woc;
    cudaGetSymbolAddress((void**)&Qp,  g_Q);
    cudaGetSymbolAddress((void**)&Kp,  g_K);
    cudaGetSymbolAddress((void**)&Vp,  g_V);
    cudaGetSymbolAddress((void**)&AOp, g_AO);
    cudaGetSymbolAddress((void**)&Xc,  g_Xc);
    cudaGetSymbolAddress((void**)&Wqc, g_Wqc);
    cudaGetSymbolAddress((void**)&Wkc, g_Wkc);
    cudaGetSymbolAddress((void**)&Wvc, g_Wvc);
    cudaGetSymbolAddress((void**)&Woc, g_Woc);

    // --- unbiased tf32 pre-rounding of GEMM inputs ---
    const int nX4 = MROWS * D_MODEL / 4;        // 2097152
    const int nW4 = D_MODEL * D_MODEL / 4;      // 262144
    round_tf32<<<nX4 / 256, 256>>>(X,  Xc,  nX4);
    round_tf32<<<nW4 / 256, 256>>>(Wq, Wqc, nW4);
    round_tf32<<<nW4 / 256, 256>>>(Wk, Wkc, nW4);
    round_tf32<<<nW4 / 256, 256>>>(Wv, Wvc, nW4);
    round_tf32<<<nW4 / 256, 256>>>(Wo, Woc, nW4);

    // --- QKV projections on tensor cores (HMMA tf32) ---
    dim3 gg(D_MODEL / 128, MROWS / 128);   // (8, 64)
    gemm_tf32mma<true><<<gg, 256>>>(Xc, Wqc, bq, Qp);
    gemm_tf32mma<true><<<gg, 256>>>(Xc, Wkc, bk, Kp);
    gemm_tf32mma<true><<<gg, 256>>>(Xc, Wvc, bv, Vp);

    // --- attention (fp32) ---
    const int smem = (64 * 129 + 64 * 65 + 64 * 64 + 128 * 65) * 4;  // 99328
    cudaFuncSetAttribute(flash_attn, cudaFuncAttributeMaxDynamicSharedMemorySize, smem);
    flash_attn<<<dim3(SEQ / 128, BATCH * NHEAD), 256, smem>>>(Qp, Kp, Vp, AOp);

    // --- output projection ---
    round_tf32<<<nX4 / 256, 256>>>(AOp, AOp, nX4);   // idempotent, in-place
    gemm_tf32mma<false><<<gg, 256>>>(AOp, Woc, bo, out);
}

// round 8
// speedup vs baseline: 2.3352x; 1.6233x over previous
#include <cuda_runtime.h>
#include <cstdint>

#define D_MODEL 1024
#define NHEAD   16
#define DK      64
#define SEQ     2048
#define BATCH   4
#define MROWS   (BATCH * SEQ)   // 8192

// ---------------------------------------------------------------------------
// Scratch (allocation-free rule: __device__ globals)
// ---------------------------------------------------------------------------
__device__ float g_Q[BATCH * NHEAD * SEQ * DK];   // [B,H,n,dk], tf32-rounded
__device__ float g_K[BATCH * NHEAD * SEQ * DK];
__device__ float g_V[BATCH * NHEAD * SEQ * DK];
__device__ float g_AO[BATCH * SEQ * D_MODEL];     // attention out, [B,n,D]
__device__ float g_Xc[MROWS * D_MODEL];           // tf32-rounded X
__device__ float g_Wqc[D_MODEL * D_MODEL];
__device__ float g_Wkc[D_MODEL * D_MODEL];
__device__ float g_Wvc[D_MODEL * D_MODEL];
__device__ float g_Woc[D_MODEL * D_MODEL];

// ---------------------------------------------------------------------------
// helpers
// ---------------------------------------------------------------------------
__device__ __forceinline__ uint32_t smem_u32(const void* p) {
    uint32_t a;
    asm("{ .reg .u64 t; cvta.to.shared.u64 t, %1; cvt.u32.u64 %0, t; }"
        : "=r"(a) : "l"(p));
    return a;
}

__device__ __forceinline__ void cp_async16(uint32_t dst, const void* src) {
    asm volatile("cp.async.cg.shared.global [%0], [%1], 16;\n" :: "r"(dst), "l"(src));
}
#define CP_COMMIT()  asm volatile("cp.async.commit_group;\n" ::: "memory")
#define CP_WAIT(N)   asm volatile("cp.async.wait_group %0;\n" :: "n"(N) : "memory")

__device__ __forceinline__ void mma_tf32(float* c, const float* a, const float* b) {
    asm volatile(
        "mma.sync.aligned.m16n8k8.row.col.f32.tf32.tf32.f32 "
        "{%0,%1,%2,%3}, {%4,%5,%6,%7}, {%8,%9}, {%0,%1,%2,%3};"
        : "+f"(c[0]), "+f"(c[1]), "+f"(c[2]), "+f"(c[3])
        : "r"(__float_as_uint(a[0])), "r"(__float_as_uint(a[1])),
          "r"(__float_as_uint(a[2])), "r"(__float_as_uint(a[3])),
          "r"(__float_as_uint(b[0])), "r"(__float_as_uint(b[1])));
}

__device__ __forceinline__ float rna_tf32(float x) {
    uint32_t u;
    asm("cvt.rna.tf32.f32 %0, %1;" : "=r"(u) : "f"(x));
    return __uint_as_float(u);
}

// ---------------------------------------------------------------------------
// Elementwise tf32 RNA rounding (unbiased).
// ---------------------------------------------------------------------------
__global__ void round_tf32(const float* __restrict__ in, float* __restrict__ out, int n4) {
    int i = blockIdx.x * blockDim.x + threadIdx.x;
    if (i < n4) {
        float4 v = ((const float4*)in)[i];
        float4 o;
        o.x = rna_tf32(v.x); o.y = rna_tf32(v.y);
        o.z = rna_tf32(v.z); o.w = rna_tf32(v.w);
        ((float4*)out)[i] = o;
    }
}

// ---------------------------------------------------------------------------
// TN GEMM on mma.sync tf32: C[m,n] = sum_k A[m,k] * W[n,k] + bias[n]
// (unchanged from passing round except: HEADOUT epilogue RNA-rounds outputs so
//  the attention kernel's tf32 mma sees exactly-representable Q/K/V.)
// ---------------------------------------------------------------------------
#define PAD 20

template <bool HEADOUT>
__global__ void __launch_bounds__(256) gemm_tf32mma(
    const float* __restrict__ A, const float* __restrict__ W,
    const float* __restrict__ bias, float* __restrict__ C)
{
    __shared__ float sA[2][128 * PAD];
    __shared__ float sB[2][128 * PAD];

    const int K = D_MODEL;
    const int tid = threadIdx.x;
    const int wid = tid >> 5;
    const int lid = tid & 31;
    const int warpM = wid >> 2;          // 0..1
    const int warpN = wid & 3;           // 0..3
    const int grp = lid >> 2;            // 0..7
    const int tig = lid & 3;             // 0..3
    const int row0 = blockIdx.y * 128;
    const int col0 = blockIdx.x * 128;

    const float* Ag = A + (size_t)row0 * K;
    const float* Wg = W + (size_t)col0 * K;

    const uint32_t aBase = smem_u32(sA);
    const uint32_t bBase = smem_u32(sB);

    const int lr = tid >> 1;
    const int lc = (tid & 1) * 8;
    const uint32_t ldst = (uint32_t)(lr * PAD + lc) * 4;

    float acc[4][4][4];
#pragma unroll
    for (int mt = 0; mt < 4; mt++)
#pragma unroll
        for (int nt = 0; nt < 4; nt++)
#pragma unroll
            for (int j = 0; j < 4; j++) acc[mt][nt][j] = 0.0f;

    {
        cp_async16(aBase + ldst,      Ag + (size_t)lr * K + lc);
        cp_async16(aBase + ldst + 16, Ag + (size_t)lr * K + lc + 4);
        cp_async16(bBase + ldst,      Wg + (size_t)lr * K + lc);
        cp_async16(bBase + ldst + 16, Wg + (size_t)lr * K + lc + 4);
        CP_COMMIT();
    }

    const int NC = K / 16;   // 64
#pragma unroll 1
    for (int c = 0; c < NC; c++) {
        const int s = c & 1;
        if (c + 1 < NC) {
            const uint32_t soff = (uint32_t)((s ^ 1) * 128 * PAD) * 4;
            const int k0 = (c + 1) * 16;
            cp_async16(aBase + soff + ldst,      Ag + (size_t)lr * K + k0 + lc);
            cp_async16(aBase + soff + ldst + 16, Ag + (size_t)lr * K + k0 + lc + 4);
            cp_async16(bBase + soff + ldst,      Wg + (size_t)lr * K + k0 + lc);
            cp_async16(bBase + soff + ldst + 16, Wg + (size_t)lr * K + k0 + lc + 4);
            CP_COMMIT();
            CP_WAIT(1);
        } else {
            CP_WAIT(0);
        }
        __syncthreads();

        const float* Ab = sA[s];
        const float* Bb = sB[s];
#pragma unroll
        for (int ks = 0; ks < 2; ks++) {
            const int kb = ks * 8;
            float af[4][4];
#pragma unroll
            for (int mt = 0; mt < 4; mt++) {
                const int rb = warpM * 64 + mt * 16;
                af[mt][0] = Ab[(rb + grp)     * PAD + kb + tig];
                af[mt][1] = Ab[(rb + grp + 8) * PAD + kb + tig];
                af[mt][2] = Ab[(rb + grp)     * PAD + kb + tig + 4];
                af[mt][3] = Ab[(rb + grp + 8) * PAD + kb + tig + 4];
            }
            float bf[4][2];
#pragma unroll
            for (int nt = 0; nt < 4; nt++) {
                const int cb = warpN * 32 + nt * 8;
                bf[nt][0] = Bb[(cb + grp) * PAD + kb + tig];
                bf[nt][1] = Bb[(cb + grp) * PAD + kb + tig + 4];
            }
#pragma unroll
            for (int mt = 0; mt < 4; mt++)
#pragma unroll
                for (int nt = 0; nt < 4; nt++)
                    mma_tf32(acc[mt][nt], af[mt], bf[nt]);
        }
        __syncthreads();
    }

#pragma unroll
    for (int mt = 0; mt < 4; mt++) {
#pragma unroll
        for (int nt = 0; nt < 4; nt++) {
            const int r  = row0 + warpM * 64 + mt * 16 + grp;
            const int cc = col0 + warpN * 32 + nt * 8 + tig * 2;
            const float b0 = bias[cc], b1 = bias[cc + 1];

            float2 v01 = make_float2(acc[mt][nt][0] + b0, acc[mt][nt][1] + b1);
            float2 v23 = make_float2(acc[mt][nt][2] + b0, acc[mt][nt][3] + b1);

            if (HEADOUT) {
                // RNA-round so flash's tf32 mma truncation is exact.
                v01.x = rna_tf32(v01.x); v01.y = rna_tf32(v01.y);
                v23.x = rna_tf32(v23.x); v23.y = rna_tf32(v23.y);
                const int b  = r >> 11;
                const int h  = cc >> 6;
                const int d0 = cc & (DK - 1);
                const size_t base = ((size_t)(b * NHEAD + h) * SEQ);
                *(float2*)(C + (base + (r & (SEQ - 1)))     * DK + d0) = v01;
                *(float2*)(C + (base + ((r + 8) & (SEQ-1))) * DK + d0) = v23;
            } else {
                *(float2*)(C + (size_t)r * D_MODEL + cc)       = v01;
                *(float2*)(C + (size_t)(r + 8) * D_MODEL + cc) = v23;
            }
        }
    }
}

// ---------------------------------------------------------------------------
// Flash attention on mma.sync tf32.
// CTA: 128 q-rows x one (b,h). 8 warps, warp tile = 16 q-rows x 64 kv (S) /
// 16 q-rows x 64 d (PV). BN=64 kv per iter, double-buffered cp.async K/V.
// Smem strides: Q/P/K = 68 (conflict-free 4*grp+tig), V = 72 ([kv][d] read
// transposed as B-frags: banks 8*tig+grp, conflict-free).
// ---------------------------------------------------------------------------
#define FQ_STR 68
#define FK_STR 68
#define FV_STR 72
#define FP_STR 68
#define F_SQ   0
#define F_SK   (128 * FQ_STR)                     // 8704
#define F_SV   (F_SK + 2 * 64 * FK_STR)           // 17408
#define F_SP   (F_SV + 2 * 64 * FV_STR)           // 26624
#define F_TOT  (F_SP + 128 * FP_STR)              // 35328 floats = 141312 B

__global__ void __launch_bounds__(256) flash_tf32(
    const float* __restrict__ Q, const float* __restrict__ Kg,
    const float* __restrict__ V, float* __restrict__ O)
{
    extern __shared__ float sm[];
    float* sQ = sm + F_SQ;
    float* sK = sm + F_SK;
    float* sV = sm + F_SV;
    float* sP = sm + F_SP;

    const int tid = threadIdx.x;
    const int wid = tid >> 5;
    const int lid = tid & 31;
    const int grp = lid >> 2;     // 0..7
    const int tig = lid & 3;      // 0..3
    const int bh = blockIdx.y;
    const int q0 = blockIdx.x * 128;
    const int rb = wid * 16;      // warp's q-row base within tile

    const float* Qp = Q  + ((size_t)bh * SEQ + q0) * DK;
    const float* Kp = Kg + (size_t)bh * SEQ * DK;
    const float* Vp = V  + (size_t)bh * SEQ * DK;

    const uint32_t sQa = smem_u32(sQ);
    const uint32_t sKa = smem_u32(sK);
    const uint32_t sVa = smem_u32(sV);

    // Q load (rows 128 x 64 floats): thread -> row tid>>1, 32-float half
    {
        const int r  = tid >> 1;
        const int c0 = (tid & 1) * 32;
#pragma unroll
        for (int j = 0; j < 8; j++)
            cp_async16(sQa + (uint32_t)(r * FQ_STR + c0 + j * 4) * 4,
                       Qp + (size_t)r * DK + c0 + j * 4);
    }
    // K/V tile 0 (64 rows x 64 floats each): thread -> row tid>>2, 16-float qtr
    {
        const int r  = tid >> 2;
        const int c0 = (tid & 3) * 16;
#pragma unroll
        for (int j = 0; j < 4; j++)
            cp_async16(sKa + (uint32_t)(r * FK_STR + c0 + j * 4) * 4,
                       Kp + (size_t)r * DK + c0 + j * 4);
#pragma unroll
        for (int j = 0; j < 4; j++)
            cp_async16(sVa + (uint32_t)(r * FV_STR + c0 + j * 4) * 4,
                       Vp + (size_t)r * DK + c0 + j * 4);
    }
    CP_COMMIT();

    float m0 = -1e30f, m1 = -1e30f, l0 = 0.0f, l1 = 0.0f;
    float oacc[8][4];
#pragma unroll
    for (int nt = 0; nt < 8; nt++)
#pragma unroll
        for (int j = 0; j < 4; j++) oacc[nt][j] = 0.0f;

    const float scale = 0.125f;   // 1/sqrt(64)
    const int NT = SEQ / 64;      // 32

#pragma unroll 1
    for (int t = 0; t < NT; t++) {
        const int s = t & 1;
        if (t + 1 < NT) {
            const int ns = s ^ 1;
            const int r  = tid >> 2;
            const int c0 = (tid & 3) * 16;
            const float* Kt = Kp + (size_t)(t + 1) * 64 * DK;
            const float* Vt = Vp + (size_t)(t + 1) * 64 * DK;
#pragma unroll
            for (int j = 0; j < 4; j++)
                cp_async16(sKa + (uint32_t)(ns * 64 * FK_STR + r * FK_STR + c0 + j * 4) * 4,
                           Kt + (size_t)r * DK + c0 + j * 4);
#pragma unroll
            for (int j = 0; j < 4; j++)
                cp_async16(sVa + (uint32_t)(ns * 64 * FV_STR + r * FV_STR + c0 + j * 4) * 4,
                           Vt + (size_t)r * DK + c0 + j * 4);
            CP_COMMIT();
            CP_WAIT(1);
        } else {
            CP_WAIT(0);
        }
        __syncthreads();

        const float* Kb = sK + s * 64 * FK_STR;
        const float* Vb = sV + s * 64 * FV_STR;

        // ---- S = scale * Q K^T -------------------------------------------
        float sf[8][4];
#pragma unroll
        for (int nt = 0; nt < 8; nt++)
#pragma unroll
            for (int j = 0; j < 4; j++) sf[nt][j] = 0.0f;

#pragma unroll
        for (int kb = 0; kb < 64; kb += 8) {
            float aq[4];
            aq[0] = sQ[(rb + grp)     * FQ_STR + kb + tig];
            aq[1] = sQ[(rb + grp + 8) * FQ_STR + kb + tig];
            aq[2] = sQ[(rb + grp)     * FQ_STR + kb + tig + 4];
            aq[3] = sQ[(rb + grp + 8) * FQ_STR + kb + tig + 4];
#pragma unroll
            for (int nt = 0; nt < 8; nt++) {
                float bk[2];
                bk[0] = Kb[(nt * 8 + grp) * FK_STR + kb + tig];
                bk[1] = Kb[(nt * 8 + grp) * FK_STR + kb + tig + 4];
                mma_tf32(sf[nt], aq, bk);
            }
        }

        // ---- online softmax (rows grp and grp+8; 4 lanes per row) --------
        float mx0 = -1e30f, mx1 = -1e30f;
#pragma unroll
        for (int nt = 0; nt < 8; nt++) {
#pragma unroll
            for (int j = 0; j < 4; j++) sf[nt][j] *= scale;
            mx0 = fmaxf(mx0, fmaxf(sf[nt][0], sf[nt][1]));
            mx1 = fmaxf(mx1, fmaxf(sf[nt][2], sf[nt][3]));
        }
        mx0 = fmaxf(mx0, __shfl_xor_sync(0xffffffffu, mx0, 1, 4));
        mx0 = fmaxf(mx0, __shfl_xor_sync(0xffffffffu, mx0, 2, 4));
        mx1 = fmaxf(mx1, __shfl_xor_sync(0xffffffffu, mx1, 1, 4));
        mx1 = fmaxf(mx1, __shfl_xor_sync(0xffffffffu, mx1, 2, 4));

        const float mn0 = fmaxf(m0, mx0);
        const float mn1 = fmaxf(m1, mx1);
        const float a0 = __expf(m0 - mn0);
        const float a1 = __expf(m1 - mn1);
        m0 = mn0; m1 = mn1;

        float rs0 = 0.0f, rs1 = 0.0f;
#pragma unroll
        for (int nt = 0; nt < 8; nt++) {
            const float p00 = rna_tf32(__expf(sf[nt][0] - mn0));
            const float p01 = rna_tf32(__expf(sf[nt][1] - mn0));
            const float p10 = rna_tf32(__expf(sf[nt][2] - mn1));
            const float p11 = rna_tf32(__expf(sf[nt][3] - mn1));
            rs0 += p00 + p01;
            rs1 += p10 + p11;
            *(float2*)&sP[(rb + grp)     * FP_STR + nt * 8 + 2 * tig] = make_float2(p00, p01);
            *(float2*)&sP[(rb + grp + 8) * FP_STR + nt * 8 + 2 * tig] = make_float2(p10, p11);
        }
        rs0 += __shfl_xor_sync(0xffffffffu, rs0, 1, 4);
        rs0 += __shfl_xor_sync(0xffffffffu, rs0, 2, 4);
        rs1 += __shfl_xor_sync(0xffffffffu, rs1, 1, 4);
        rs1 += __shfl_xor_sync(0xffffffffu, rs1, 2, 4);
        l0 = l0 * a0 + rs0;
        l1 = l1 * a1 + rs1;

#pragma unroll
        for (int nt = 0; nt < 8; nt++) {
            oacc[nt][0] *= a0; oacc[nt][1] *= a0;
            oacc[nt][2] *= a1; oacc[nt][3] *= a1;
        }
        __syncthreads();   // P visible to all lanes of this warp's tile rows

        // ---- O += P V  (contraction over kv; B-frags transposed from V) --
#pragma unroll
        for (int kb = 0; kb < 64; kb += 8) {
            float ap[4];
            ap[0] = sP[(rb + grp)     * FP_STR + kb + tig];
            ap[1] = sP[(rb + grp + 8) * FP_STR + kb + tig];
            ap[2] = sP[(rb + grp)     * FP_STR + kb + tig + 4];
            ap[3] = sP[(rb + grp + 8) * FP_STR + kb + tig + 4];
#pragma unroll
            for (int nt = 0; nt < 8; nt++) {
                float bv[2];
                bv[0] = Vb[(kb + tig)     * FV_STR + nt * 8 + grp];
                bv[1] = Vb[(kb + tig + 4) * FV_STR + nt * 8 + grp];
                mma_tf32(oacc[nt], ap, bv);
            }
        }
        __syncthreads();   // PV done: safe to prefetch into other buffer
    }

    // ---- epilogue: O /= l, write [B,n,D_MODEL] ---------------------------
    const int b = bh >> 4;
    const int h = bh & (NHEAD - 1);
    const int r0g = q0 + rb + grp;
    const int r1g = r0g + 8;
    const float inv0 = 1.0f / l0;
    const float inv1 = 1.0f / l1;
#pragma unroll
    for (int nt = 0; nt < 8; nt++) {
        float2 v0 = make_float2(oacc[nt][0] * inv0, oacc[nt][1] * inv0);
        float2 v1 = make_float2(oacc[nt][2] * inv1, oacc[nt][3] * inv1);
        const int cc = h * DK + nt * 8 + 2 * tig;
        *(float2*)(O + ((size_t)b * SEQ + r0g) * D_MODEL + cc) = v0;
        *(float2*)(O + ((size_t)b * SEQ + r1g) * D_MODEL + cc) = v1;
    }
}

// ---------------------------------------------------------------------------
extern "C" void kernel_launch(void* const* d_in, const int* in_sizes, int n_in,
                              void* d_out, int out_size)
{
    const float* X  = (const float*)d_in[0];
    const float* Wq = (const float*)d_in[1];
    const float* bq = (const float*)d_in[2];
    const float* Wk = (const float*)d_in[3];
    const float* bk = (const float*)d_in[4];
    const float* Wv = (const float*)d_in[5];
    const float* bv = (const float*)d_in[6];
    const float* Wo = (const float*)d_in[7];
    const float* bo = (const float*)d_in[8];
    float* out = (float*)d_out;

    float *Qp, *Kp, *Vp, *AOp, *Xc, *Wqc, *Wkc, *Wvc, *Woc;
    cudaGetSymbolAddress((void**)&Qp,  g_Q);
    cudaGetSymbolAddress((void**)&Kp,  g_K);
    cudaGetSymbolAddress((void**)&Vp,  g_V);
    cudaGetSymbolAddress((void**)&AOp, g_AO);
    cudaGetSymbolAddress((void**)&Xc,  g_Xc);
    cudaGetSymbolAddress((void**)&Wqc, g_Wqc);
    cudaGetSymbolAddress((void**)&Wkc, g_Wkc);
    cudaGetSymbolAddress((void**)&Wvc, g_Wvc);
    cudaGetSymbolAddress((void**)&Woc, g_Woc);

    // --- unbiased tf32 pre-rounding of GEMM inputs ---
    const int nX4 = MROWS * D_MODEL / 4;        // 2097152
    const int nW4 = D_MODEL * D_MODEL / 4;      // 262144
    round_tf32<<<nX4 / 256, 256>>>(X,  Xc,  nX4);
    round_tf32<<<nW4 / 256, 256>>>(Wq, Wqc, nW4);
    round_tf32<<<nW4 / 256, 256>>>(Wk, Wkc, nW4);
    round_tf32<<<nW4 / 256, 256>>>(Wv, Wvc, nW4);
    round_tf32<<<nW4 / 256, 256>>>(Wo, Woc, nW4);

    // --- QKV projections on tensor cores (HMMA tf32); outputs RNA-rounded ---
    dim3 gg(D_MODEL / 128, MROWS / 128);   // (8, 64)
    gemm_tf32mma<true><<<gg, 256>>>(Xc, Wqc, bq, Qp);
    gemm_tf32mma<true><<<gg, 256>>>(Xc, Wkc, bk, Kp);
    gemm_tf32mma<true><<<gg, 256>>>(Xc, Wvc, bv, Vp);

    // --- attention on tensor cores (tf32) ---
    const int fsmem = F_TOT * 4;   // 141312
    cudaFuncSetAttribute(flash_tf32, cudaFuncAttributeMaxDynamicSharedMemorySize, fsmem);
    flash_tf32<<<dim3(SEQ / 128, BATCH * NHEAD), 256, fsmem>>>(Qp, Kp, Vp, AOp);

    // --- output projection ---
    round_tf32<<<nX4 / 256, 256>>>(AOp, AOp, nX4);   // idempotent, in-place
    gemm_tf32mma<false><<<gg, 256>>>(AOp, Woc, bo, out);
}